// round 5
// baseline (speedup 1.0000x reference)
#include <cuda_runtime.h>
#include <math.h>

#define BB 16
#define HH 512
#define WW 512
#define NTOT (BB * HH * WW)

#define TILE 64
#define GX (WW / TILE)      // 8
#define GY (HH / TILE)      // 8
#define NB (GX * GY * BB)   // 1024
#define LCAP 256
#define HROWS 84            // rows i0-10 .. i0+73
#define HC4 22              // 22 float4 col-groups: cols j0-12 .. j0+75

// Scratch (no allocation allowed in kernel_launch)
__device__ float g_pl[NB];
__device__ float g_pf[NB];
__device__ unsigned g_done = 0;  // last-block counter (self-resetting)

// ---------------------------------------------------------------------------
// Single fused kernel. Per 64x64 tile:
//  1) scan tgt halo (84x88, float4 loads) -> point list in smem (~7 pts)
//  2) scatter each point's disc (dd<=100) into sdmin[64*64] via atomicMin
//     (order-independent -> deterministic)
//  3) per-pixel: p=sigmoid(inp), h=slut[dmin] (LUT), accumulate
//     fsum += p^2, lsum += (p*(p-h))^2 ; scale by 0.15 once.
//     pos pixels (dmin==0 <=> fg, h=1 exact) get pixel-owned corrections:
//     cf = 0.85(1-p)^2 - 0.15p^2, cl = (1-p)^2*cf  (rare branch).
//  4) block reduction -> partials; last block folds the final scalar.
// Pixels with no point within dist 10 get dmin=400 -> h=exp(-50)~0; true
// heatmap there is <= exp(-100/8)=3.7e-6 -> loss-equivalent within 1e-5.
// ---------------------------------------------------------------------------
__global__ __launch_bounds__(256) void k_fused(const float* __restrict__ inp,
                                               const float* __restrict__ tgt,
                                               float* __restrict__ out) {
    const int tid = threadIdx.x;
    const int tx = tid & 31;
    const int ty = tid >> 5;
    const int j0 = blockIdx.x * TILE;
    const int i0 = blockIdx.y * TILE;
    const int b = blockIdx.z;

    __shared__ int sdmin[TILE * TILE];  // 16 KB
    __shared__ float slut[401];
    __shared__ unsigned slist[LCAP];
    __shared__ int scnt;
    __shared__ int slast;
    __shared__ float sredF[256];
    __shared__ float sredL[256];
    __shared__ double sFd[256];
    __shared__ double sLd[256];

    if (tid == 0) scnt = 0;
    // heatmap LUT: h = exp(-dmin/8); slut[0] = 1 exactly
    for (int i = tid; i < 401; i += 256) slut[i] = __expf((float)i * -0.125f);
    // dmin init
#pragma unroll
    for (int k = 0; k < 16; k++) sdmin[tid + 256 * k] = 400;
    __syncthreads();

    // --- 1) scan tgt halo, build point list (halo coords r:0..83, c:0..87) ---
    const float* tb = tgt + (size_t)b * HH * WW;
    for (int e = tid; e < HROWS * HC4; e += 256) {
        int rr = e / HC4;
        int k4 = e - rr * HC4;
        int gr = i0 - 10 + rr;
        int gc = j0 - 12 + 4 * k4;
        if ((unsigned)gr < HH && (unsigned)gc <= (WW - 4)) {
            float4 v = *(const float4*)(tb + (size_t)gr * WW + gc);
            if (v.x > 0.5f || v.y > 0.5f || v.z > 0.5f || v.w > 0.5f) {
                int cb = 4 * k4;
                if (v.x > 0.5f) { int k = atomicAdd(&scnt, 1); if (k < LCAP) slist[k] = (rr << 8) | cb; }
                if (v.y > 0.5f) { int k = atomicAdd(&scnt, 1); if (k < LCAP) slist[k] = (rr << 8) | (cb + 1); }
                if (v.z > 0.5f) { int k = atomicAdd(&scnt, 1); if (k < LCAP) slist[k] = (rr << 8) | (cb + 2); }
                if (v.w > 0.5f) { int k = atomicAdd(&scnt, 1); if (k < LCAP) slist[k] = (rr << 8) | (cb + 3); }
            }
        }
    }
    __syncthreads();
    const int L = min(scnt, LCAP);

    // --- 2) scatter discs into sdmin ---
    for (int it = tid; it < L * 441; it += 256) {
        int p = it / 441;
        int e = it - p * 441;
        unsigned pk = slist[p];
        int rp = (int)(pk >> 8);
        int cp = (int)(pk & 255u);
        int di = e / 21;
        int dj = e - di * 21;
        di -= 10;
        dj -= 10;
        int dd = di * di + dj * dj;
        int tr = rp - 10 + di;  // tile row
        int tc = cp - 12 + dj;  // tile col
        if (dd <= 100 && (unsigned)tr < TILE && (unsigned)tc < TILE)
            atomicMin(&sdmin[tr * TILE + tc], dd);
    }
    __syncthreads();

    // --- 3) per-pixel epilogue: 8 rows x 2 cols per thread ---
    const int r0 = ty * 8;
    const float* ib = inp + ((size_t)(b * HH + i0 + r0)) * WW + j0 + 2 * tx;
    float fsum = 0.0f, lsum = 0.0f;
    int mnall = 400;
#pragma unroll
    for (int mm = 0; mm < 8; mm++) {
        int2 dm = *(const int2*)&sdmin[(r0 + mm) * TILE + 2 * tx];
        float2 x2 = *(const float2*)(ib + (size_t)mm * WW);
        float h0 = slut[dm.x];
        float h1 = slut[dm.y];
        mnall = min(mnall, min(dm.x, dm.y));
        float p0 = __fdividef(1.0f, 1.0f + __expf(-x2.x));
        float p1 = __fdividef(1.0f, 1.0f + __expf(-x2.y));
        fsum += p0 * p0 + p1 * p1;
        float t0 = p0 * (p0 - h0);
        float t1 = p1 * (p1 - h1);
        lsum += t0 * t0 + t1 * t1;
    }
    float thF = 0.15f * fsum;
    float thL = 0.15f * lsum;

    if (mnall == 0) {  // rare: this thread owns >=1 foreground pixel
        for (int mm = 0; mm < 8; mm++) {
            int2 dm = *(const int2*)&sdmin[(r0 + mm) * TILE + 2 * tx];
            float2 x2 = *(const float2*)(ib + (size_t)mm * WW);
            if (dm.x == 0) {
                float p = __fdividef(1.0f, 1.0f + __expf(-x2.x));
                float q = 1.0f - p;
                float cf = 0.85f * q * q - 0.15f * p * p;
                thF += cf;
                thL += q * q * cf;
            }
            if (dm.y == 0) {
                float p = __fdividef(1.0f, 1.0f + __expf(-x2.y));
                float q = 1.0f - p;
                float cf = 0.85f * q * q - 0.15f * p * p;
                thF += cf;
                thL += q * q * cf;
            }
        }
    }

    // --- 4) block reduction + last-block finalize ---
    sredF[tid] = thF;
    sredL[tid] = thL;
    __syncthreads();
#pragma unroll
    for (int s = 128; s > 0; s >>= 1) {
        if (tid < s) {
            sredF[tid] += sredF[tid + s];
            sredL[tid] += sredL[tid + s];
        }
        __syncthreads();
    }

    const int bid = blockIdx.x + GX * (blockIdx.y + GY * blockIdx.z);
    if (tid == 0) {
        g_pf[bid] = sredF[0];
        g_pl[bid] = sredL[0];
        __threadfence();
        unsigned old = atomicAdd(&g_done, 1u);
        slast = (old == NB - 1) ? 1 : 0;
    }
    __syncthreads();

    if (slast) {
        __threadfence();
        double f = 0.0, l = 0.0;
        for (int i = tid; i < NB; i += 256) {
            f += (double)g_pf[i];
            l += (double)g_pl[i];
        }
        sFd[tid] = f;
        sLd[tid] = l;
        __syncthreads();
#pragma unroll
        for (int s = 128; s > 0; s >>= 1) {
            if (tid < s) {
                sFd[tid] += sFd[tid + s];
                sLd[tid] += sLd[tid + s];
            }
            __syncthreads();
        }
        if (tid == 0) {
            double n = (double)NTOT;
            double denom = sFd[0] / n + 0.01;
            out[0] = (float)(2.0 * (sLd[0] / n) / denom);
            g_done = 0;  // reset for next graph replay
        }
    }
}

extern "C" void kernel_launch(void* const* d_in, const int* in_sizes, int n_in,
                              void* d_out, int out_size) {
    const float* inp = (const float*)d_in[0];
    const float* tgt = (const float*)d_in[1];
    float* out = (float*)d_out;

    dim3 g(GX, GY, BB);
    k_fused<<<g, 256>>>(inp, tgt, out);
}

// round 6
// speedup vs baseline: 1.1901x; 1.1901x over previous
#include <cuda_runtime.h>
#include <math.h>

#define BB 16
#define HH 512
#define WW 512
#define NTOT (BB * HH * WW)

#define TILE 64
#define GX (WW / TILE)     // 8
#define GY (HH / TILE)     // 8
#define NB (GX * GY * BB)  // 1024
#define LCAP 256
#define HROWS 84           // halo rows i0-10 .. i0+73

// Scratch (no allocation allowed in kernel_launch)
__device__ unsigned g_mask[BB * HH * 16];  // fg bitmask, 16 u32 words per row
__device__ float g_pl[NB];
__device__ float g_pf[NB];
__device__ unsigned g_done = 0;  // last-block counter (self-resetting)

// ---------------------------------------------------------------------------
// K1: build fg bitmask. Pure streaming: each thread loads 4 independent
// float4s (16 cols), builds 16 bits locally, stores one u16. MLP=4/thread.
// ---------------------------------------------------------------------------
__global__ __launch_bounds__(256) void k1_mask(const float* __restrict__ tgt) {
    const int gid = blockIdx.x * 256 + threadIdx.x;
    const int row = gid >> 5;
    const int c16 = gid & 31;
    const float4* p = (const float4*)(tgt + (size_t)row * WW + c16 * 16);
    float4 v0 = p[0], v1 = p[1], v2 = p[2], v3 = p[3];
    unsigned m = 0;
    m |= (v0.x > 0.5f) ? 1u << 0 : 0u;
    m |= (v0.y > 0.5f) ? 1u << 1 : 0u;
    m |= (v0.z > 0.5f) ? 1u << 2 : 0u;
    m |= (v0.w > 0.5f) ? 1u << 3 : 0u;
    m |= (v1.x > 0.5f) ? 1u << 4 : 0u;
    m |= (v1.y > 0.5f) ? 1u << 5 : 0u;
    m |= (v1.z > 0.5f) ? 1u << 6 : 0u;
    m |= (v1.w > 0.5f) ? 1u << 7 : 0u;
    m |= (v2.x > 0.5f) ? 1u << 8 : 0u;
    m |= (v2.y > 0.5f) ? 1u << 9 : 0u;
    m |= (v2.z > 0.5f) ? 1u << 10 : 0u;
    m |= (v2.w > 0.5f) ? 1u << 11 : 0u;
    m |= (v3.x > 0.5f) ? 1u << 12 : 0u;
    m |= (v3.y > 0.5f) ? 1u << 13 : 0u;
    m |= (v3.z > 0.5f) ? 1u << 14 : 0u;
    m |= (v3.w > 0.5f) ? 1u << 15 : 0u;
    ((unsigned short*)g_mask)[(size_t)row * 32 + c16] = (unsigned short)m;
}

// ---------------------------------------------------------------------------
// K2: per 64x64 tile.
//  1) extract fg points (tile+10 halo) straight from the L2-resident bitmask
//  2) scatter each point's disc (dd<=100) into sdmin via atomicMin; each
//     thread owns 2 FIXED disc cells -> geometry hoisted out of the loop
//  3) per-pixel: p=sigmoid(inp), h=slut[dmin]; uniform path
//     fsum += p^2, lsum += (p(p-h))^2, scaled by 0.15; pos pixels
//     (dmin==0, h=1 exact) add cf = 0.85q^2-0.15p^2, cl = q^2*cf (rare).
//  4) shuffle reduction -> partials; last block folds the final scalar.
// dmin=400 where no point within dist 10 -> h=exp(-50)~0; true heatmap
// there <= exp(-100/8)=3.7e-6 -> loss-equivalent well within 1e-3.
// ---------------------------------------------------------------------------
__global__ __launch_bounds__(256) void k2_main(const float* __restrict__ inp,
                                               float* __restrict__ out) {
    const int tid = threadIdx.x;
    const int tx = tid & 31;
    const int ty = tid >> 5;
    const int j0 = blockIdx.x * TILE;
    const int i0 = blockIdx.y * TILE;
    const int b = blockIdx.z;

    __shared__ __align__(16) int sdmin[TILE * TILE];  // 16 KB (reused in finalize)
    __shared__ float slut[401];
    __shared__ unsigned slist[LCAP];
    __shared__ int scnt;
    __shared__ int slast;
    __shared__ float swF[8];
    __shared__ float swL[8];

    if (tid == 0) scnt = 0;
    for (int i = tid; i < 401; i += 256) slut[i] = __expf((float)i * -0.125f);
#pragma unroll
    for (int k = 0; k < 16; k++) sdmin[tid + 256 * k] = 400;

    // per-thread fixed disc cells: e = tid and tid+256 of the 21x21 disc
    // cell e: di = e/21 - 10, dj = e%21 - 10; target = (rp + di - 20, cp + dj - 20)
    int diM0, djM0, dd0, ok0, diM1, djM1, dd1, ok1;
    {
        int e0 = tid;
        int a = e0 / 21, c = e0 - a * 21;
        int di = a - 10, dj = c - 10;
        dd0 = di * di + dj * dj;
        ok0 = dd0 <= 100;
        diM0 = di - 10;  // rp + diM0 = tile row
        djM0 = dj - 10;
        int e1 = tid + 256;
        a = e1 / 21;
        c = e1 - a * 21;
        di = a - 10;
        dj = c - 10;
        dd1 = di * di + dj * dj;
        ok1 = (e1 < 441) && (dd1 <= 100);
        diM1 = di - 10;
        djM1 = dj - 10;
    }
    __syncthreads();  // scnt, sdmin, slut ready

    // --- 1) extract points from bitmask (rows i0-10..i0+73, 4 words/row) ---
    const int q = j0 >> 5;
    const unsigned* mb = g_mask + (size_t)b * HH * 16;
    for (int e = tid; e < HROWS * 4; e += 256) {
        int rr = e >> 2;
        int wi = e & 3;
        int gr = i0 - 10 + rr;
        int gw = q - 1 + wi;
        unsigned v = 0;
        if ((unsigned)gr < HH && (unsigned)gw < 16u) v = mb[gr * 16 + gw];
        if (wi == 0) v &= 0xFFC00000u;  // keep cols >= j0-10
        if (wi == 3) v &= 0x000003FFu;  // keep cols <= j0+73
        while (v) {
            int bit = __ffs(v) - 1;
            v &= v - 1;
            int ch = 32 * wi + bit - 22;  // halo col 0..83
            int k = atomicAdd(&scnt, 1);
            if (k < LCAP) slist[k] = ((unsigned)rr << 8) | (unsigned)ch;
        }
    }
    __syncthreads();
    const int L = min(scnt, LCAP);

    // --- 2) scatter discs (order-independent atomicMin -> deterministic) ---
    for (int p = 0; p < L; p++) {
        unsigned pk = slist[p];
        int rp = (int)(pk >> 8);
        int cp = (int)(pk & 255u);
        if (ok0) {
            int tr = rp + diM0, tc = cp + djM0;
            if ((unsigned)tr < TILE && (unsigned)tc < TILE)
                atomicMin(&sdmin[tr * TILE + tc], dd0);
        }
        if (ok1) {
            int tr = rp + diM1, tc = cp + djM1;
            if ((unsigned)tr < TILE && (unsigned)tc < TILE)
                atomicMin(&sdmin[tr * TILE + tc], dd1);
        }
    }
    __syncthreads();

    // --- 3) epilogue: 8 rows x 2 cols per thread ---
    const int r0 = ty * 8;
    const float* ib = inp + ((size_t)(b * HH + i0 + r0)) * WW + j0 + 2 * tx;
    float fsum = 0.0f, lsum = 0.0f;
    int mnall = 400;
#pragma unroll
    for (int mm = 0; mm < 8; mm++) {
        int2 dm = *(const int2*)&sdmin[(r0 + mm) * TILE + 2 * tx];
        float2 x2 = *(const float2*)(ib + (size_t)mm * WW);
        float h0 = slut[dm.x];
        float h1 = slut[dm.y];
        mnall = min(mnall, min(dm.x, dm.y));
        float p0 = __fdividef(1.0f, 1.0f + __expf(-x2.x));
        float p1 = __fdividef(1.0f, 1.0f + __expf(-x2.y));
        fsum += p0 * p0 + p1 * p1;
        float t0 = p0 * (p0 - h0);
        float t1 = p1 * (p1 - h1);
        lsum += t0 * t0 + t1 * t1;
    }
    float thF = 0.15f * fsum;
    float thL = 0.15f * lsum;

    if (mnall == 0) {  // rare: thread owns >=1 foreground pixel
        for (int mm = 0; mm < 8; mm++) {
            int2 dm = *(const int2*)&sdmin[(r0 + mm) * TILE + 2 * tx];
            float2 x2 = *(const float2*)(ib + (size_t)mm * WW);
            if (dm.x == 0) {
                float p = __fdividef(1.0f, 1.0f + __expf(-x2.x));
                float qq = 1.0f - p;
                float cf = 0.85f * qq * qq - 0.15f * p * p;
                thF += cf;
                thL += qq * qq * cf;
            }
            if (dm.y == 0) {
                float p = __fdividef(1.0f, 1.0f + __expf(-x2.y));
                float qq = 1.0f - p;
                float cf = 0.85f * qq * qq - 0.15f * p * p;
                thF += cf;
                thL += qq * qq * cf;
            }
        }
    }

    // --- 4) shuffle reduction (fixed order -> deterministic) ---
#pragma unroll
    for (int off = 16; off > 0; off >>= 1) {
        thF += __shfl_xor_sync(0xffffffffu, thF, off);
        thL += __shfl_xor_sync(0xffffffffu, thL, off);
    }
    if (tx == 0) {
        swF[ty] = thF;
        swL[ty] = thL;
    }
    __syncthreads();

    const int bid = blockIdx.x + GX * (blockIdx.y + GY * blockIdx.z);
    if (tid == 0) {
        float F = 0.0f, Lv = 0.0f;
#pragma unroll
        for (int w = 0; w < 8; w++) {
            F += swF[w];
            Lv += swL[w];
        }
        g_pf[bid] = F;
        g_pl[bid] = Lv;
        __threadfence();
        unsigned old = atomicAdd(&g_done, 1u);
        slast = (old == NB - 1) ? 1 : 0;
    }
    __syncthreads();

    // --- last block: fold final scalar (reuses sdmin as double scratch) ---
    if (slast) {
        __threadfence();
        double* sFd = (double*)sdmin;        // 256 doubles
        double* sLd = ((double*)sdmin) + 256;
        double f = 0.0, l = 0.0;
        for (int i = tid; i < NB; i += 256) {
            f += (double)g_pf[i];
            l += (double)g_pl[i];
        }
        sFd[tid] = f;
        sLd[tid] = l;
        __syncthreads();
#pragma unroll
        for (int s = 128; s > 0; s >>= 1) {
            if (tid < s) {
                sFd[tid] += sFd[tid + s];
                sLd[tid] += sLd[tid + s];
            }
            __syncthreads();
        }
        if (tid == 0) {
            double n = (double)NTOT;
            double denom = sFd[0] / n + 0.01;
            out[0] = (float)(2.0 * (sLd[0] / n) / denom);
            g_done = 0;  // reset for next graph replay
        }
    }
}

extern "C" void kernel_launch(void* const* d_in, const int* in_sizes, int n_in,
                              void* d_out, int out_size) {
    const float* inp = (const float*)d_in[0];
    const float* tgt = (const float*)d_in[1];
    float* out = (float*)d_out;

    k1_mask<<<(BB * HH * 32) / 256, 256>>>(tgt);
    dim3 g2(GX, GY, BB);
    k2_main<<<g2, 256>>>(inp, out);
}